// round 12
// baseline (speedup 1.0000x reference)
#include <cuda_runtime.h>
#include <cstdint>

// NOGLSTM: B=64, T=512, D=256, U=512
#define B_  64
#define T_  512
#define D_  256
#define U_  512
#define GROUPS 8          // batch groups (8 rows each)
#define CPG    16         // CTAs per group
#define RTHREADS 384      // recurrence kernel threads

typedef unsigned long long ull;

// ----------------------------- device scratch ------------------------------
__device__ float g_xproj[(size_t)T_ * B_ * 3 * U_];   // [t][b][gate][u]
__device__ float g_h[2 * GROUPS * 8 * U_];            // [buf][g][r][u]
__device__ int   g_cnt[GROUPS * 32];                  // padded counters

// ----------------------------- helpers -------------------------------------
__device__ __forceinline__ void fma2(ull& acc, ull a, ull b) {
    asm("fma.rn.f32x2 %0, %1, %2, %0;" : "+l"(acc) : "l"(a), "l"(b));
}
__device__ __forceinline__ ull dup2(float v) {
    ull r; asm("mov.b64 %0, {%1, %1};" : "=l"(r) : "f"(v)); return r;
}
__device__ __forceinline__ void unpack2(ull v, float& lo, float& hi) {
    asm("mov.b64 {%0, %1}, %2;" : "=f"(lo), "=f"(hi) : "l"(v));
}
__device__ __forceinline__ float sigmoid_f(float x) {
    return __fdividef(1.f, 1.f + __expf(-x));
}
__device__ __forceinline__ float tanh_f(float x) {
    float e = __expf(2.f * x);
    return 1.f - __fdividef(2.f, e + 1.f);
}

// ============================================================================
// init: reset counters, load h0 into buffer 0
// ============================================================================
__global__ void init_kernel(const float* __restrict__ h0) {
    int tid = blockIdx.x * blockDim.x + threadIdx.x;
    if (tid < GROUPS * 32) g_cnt[tid] = 0;
    for (int i = tid; i < B_ * U_; i += gridDim.x * blockDim.x)
        g_h[i] = h0[i];   // [buf0][g][r][u] == [b][u] since b = g*8+r
}

// ============================================================================
// Phase 1: xproj = x @ w_x* + b_*   (f32x2 tiled GEMM)
// grid = (U/128=4, 32768/128=256, 3), block = 256
// ============================================================================
__global__ __launch_bounds__(256, 2) void xproj_kernel(
    const float* __restrict__ x,
    const float* __restrict__ wi, const float* __restrict__ wf, const float* __restrict__ wc,
    const float* __restrict__ bi, const float* __restrict__ bf, const float* __restrict__ bc)
{
    __shared__ float As[8][128];   // [k][m]
    __shared__ float Bs[8][128];   // [k][n]

    const int gate = blockIdx.z;
    const float* w    = (gate == 0) ? wi : (gate == 1) ? wf : wc;
    const float* bias = (gate == 0) ? bi : (gate == 1) ? bf : bc;

    const int mBase = blockIdx.y * 128;
    const int uBase = blockIdx.x * 128;
    const int tid = threadIdx.x;
    const int tx = tid & 15;
    const int ty = tid >> 4;

    const int aRow = tid >> 1, aK = (tid & 1) * 4;
    const int bK = tid >> 5, bCol = (tid & 31) * 4;

    ull acc[8][4];
    #pragma unroll
    for (int i = 0; i < 8; ++i)
        #pragma unroll
        for (int j = 0; j < 4; ++j) acc[i][j] = 0ull;

    float4 aReg = *(const float4*)&x[(size_t)(mBase + aRow) * D_ + aK];
    float4 bReg = *(const float4*)&w[(size_t)bK * U_ + uBase + bCol];

    for (int kt = 0; kt < D_ / 8; ++kt) {
        __syncthreads();
        As[aK + 0][aRow] = aReg.x;
        As[aK + 1][aRow] = aReg.y;
        As[aK + 2][aRow] = aReg.z;
        As[aK + 3][aRow] = aReg.w;
        *(float4*)&Bs[bK][bCol] = bReg;
        __syncthreads();
        if (kt + 1 < D_ / 8) {
            aReg = *(const float4*)&x[(size_t)(mBase + aRow) * D_ + (kt + 1) * 8 + aK];
            bReg = *(const float4*)&w[(size_t)((kt + 1) * 8 + bK) * U_ + uBase + bCol];
        }
        #pragma unroll
        for (int k = 0; k < 8; ++k) {
            float4 aA = *(const float4*)&As[k][ty * 4];
            float4 aB = *(const float4*)&As[k][64 + ty * 4];
            ulonglong2 b0 = *(const ulonglong2*)&Bs[k][tx * 4];
            ulonglong2 b1 = *(const ulonglong2*)&Bs[k][64 + tx * 4];
            float av[8] = {aA.x, aA.y, aA.z, aA.w, aB.x, aB.y, aB.z, aB.w};
            #pragma unroll
            for (int i = 0; i < 8; ++i) {
                ull ad = dup2(av[i]);
                fma2(acc[i][0], ad, b0.x);
                fma2(acc[i][1], ad, b0.y);
                fma2(acc[i][2], ad, b1.x);
                fma2(acc[i][3], ad, b1.y);
            }
        }
    }

    float4 biasA = *(const float4*)&bias[uBase + tx * 4];
    float4 biasB = *(const float4*)&bias[uBase + 64 + tx * 4];

    #pragma unroll
    for (int i = 0; i < 8; ++i) {
        int m = (i < 4) ? (mBase + ty * 4 + i) : (mBase + 64 + ty * 4 + (i - 4));
        int tt = m & (T_ - 1);
        int bb = m >> 9;
        float l0, h0v, l1, h1v;
        unpack2(acc[i][0], l0, h0v);
        unpack2(acc[i][1], l1, h1v);
        float4 v0 = {l0 + biasA.x, h0v + biasA.y, l1 + biasA.z, h1v + biasA.w};
        unpack2(acc[i][2], l0, h0v);
        unpack2(acc[i][3], l1, h1v);
        float4 v1 = {l0 + biasB.x, h0v + biasB.y, l1 + biasB.z, h1v + biasB.w};
        float* op = g_xproj + ((size_t)(tt * B_ + bb) * 3 + gate) * U_;
        *(float4*)&op[uBase + tx * 4]      = v0;
        *(float4*)&op[uBase + 64 + tx * 4] = v1;
    }
}

// ============================================================================
// Phase 2: persistent recurrence. 128 CTAs = 8 groups x 16. 384 threads.
// smem: Wp[48][514] float2 (col-pair x k, W_h slice, resident whole kernel)
//       hd[8][514] ull    (h duplicated as f32x2; refilled each step)
//       pa (aliased on hd): float [2][96][9] partial preactivations
// Lane mapping (GEMM): w = tid>>5; ks = w&1 (K half); cpg = w>>1 (col-pair
// group of 8); cp = cpg*8 + (lane&7); rp = lane>>3 -> rows 2rp, 2rp+1.
// acc0/acc1 = f32x2 over cols (2cp, 2cp+1) for rows 2rp / 2rp+1.
// ============================================================================
#define WP_STRIDE 514       // float2 units
#define HD_STRIDE 514       // ull units
#define WP_BYTES (48 * WP_STRIDE * 8)                 // 197376
#define HD_BYTES (8 * HD_STRIDE * 8)                  // 32896
#define RSMEM    (WP_BYTES + HD_BYTES)                // 230272

__global__ __launch_bounds__(RTHREADS, 1) void recur_kernel(
    const float* __restrict__ whi, const float* __restrict__ whf,
    const float* __restrict__ whc, const float* __restrict__ c0,
    float* __restrict__ out)
{
    extern __shared__ char smem_raw[];
    float2* Wp = (float2*)smem_raw;
    ull*    hd = (ull*)(smem_raw + WP_BYTES);
    float*  pa = (float*)(smem_raw + WP_BYTES);        // aliased on hd

    const int tid = threadIdx.x;
    const int g   = blockIdx.x >> 4;                   // group
    const int cg  = blockIdx.x & 15;                   // CTA in group
    const int u_base = cg * 32;

    // ---- load W_h slice into smem as col-pairs: Wp[cp][k] ----
    for (int idx = tid; idx < 48 * 512; idx += RTHREADS) {
        int cp = idx % 48;
        int k  = idx / 48;
        int gate = cp >> 4;
        int u = u_base + ((cp & 15) << 1);
        const float* wsrc = (gate == 0) ? whi : (gate == 1) ? whf : whc;
        Wp[cp * WP_STRIDE + k] = *(const float2*)&wsrc[(size_t)k * U_ + u];
    }

    // ---- per-thread epilogue state (tid < 256): r = tid>>5, u = tid&31 ----
    const int er = tid >> 5;
    const int eu = tid & 31;
    const int b  = g * 8 + er;            // batch row
    const int ug = u_base + eu;           // global unit
    float cst = 0.f;
    if (tid < 256) cst = c0[(size_t)b * U_ + ug];

    // ---- GEMM lane mapping ----
    const int w    = tid >> 5;
    const int lane = tid & 31;
    const int ks   = w & 1;
    const int cpg  = w >> 1;
    const int cp   = cpg * 8 + (lane & 7);
    const int rp   = lane >> 3;
    const float2* wp_l = Wp + cp * WP_STRIDE;
    const ull* hr0 = hd + (2 * rp) * HD_STRIDE;
    const ull* hr1 = hd + (2 * rp + 1) * HD_STRIDE;
    const int k0 = ks * 256;

    // ---- preload hd with h_0 from g_h[0] ----
    {
        const float* gh = g_h + (size_t)g * 8 * U_;    // buf 0
        for (int idx = tid; idx < 8 * U_; idx += RTHREADS) {
            int r = idx >> 9, k = idx & (U_ - 1);
            hd[r * HD_STRIDE + k] = dup2(__ldcg(&gh[idx]));
        }
    }
    __syncthreads();

    volatile int* vcnt = &g_cnt[g * 32];

    for (int t = 0; t < T_; ++t) {
        const int nbuf = (t + 1) & 1;

        // prefetch xproj for this step (hidden under GEMM)
        float xi = 0.f, xf = 0.f, xc = 0.f;
        if (tid < 256) {
            const float* xp = g_xproj + ((size_t)(t * B_ + b) * 3) * U_ + ug;
            xi = __ldg(xp);
            xf = __ldg(xp + U_);
            xc = __ldg(xp + 2 * U_);
        }

        // ---- GEMM: preact[r][col] partials over K half ----
        ull a0 = 0ull, a1 = 0ull;
        #pragma unroll 8
        for (int k = k0; k < k0 + 256; k += 2) {
            ulonglong2 wv = *(const ulonglong2*)&wp_l[k];   // (W[k][c0,c1]),(W[k+1][c0,c1])
            ulonglong2 h0v = *(const ulonglong2*)&hr0[k];
            ulonglong2 h1v = *(const ulonglong2*)&hr1[k];
            fma2(a0, h0v.x, wv.x);
            fma2(a0, h0v.y, wv.y);
            fma2(a1, h1v.x, wv.x);
            fma2(a1, h1v.y, wv.y);
        }
        __syncthreads();   // all warps done reading hd (pa aliases it)

        // store partials: pa[ks][col][r], col stride 9 (bank-conflict-free)
        {
            float v00, v01, v10, v11;
            unpack2(a0, v00, v01);
            unpack2(a1, v10, v11);
            float* p = pa + (ks * 96 + 2 * cp) * 9;
            p[2 * rp]     = v00;   // col 2cp,   row 2rp
            p[2 * rp + 1] = v10;   // col 2cp,   row 2rp+1
            p[9 + 2 * rp]     = v01;
            p[9 + 2 * rp + 1] = v11;
        }
        __syncthreads();

        // ---- epilogue: gates, state update, h exchange ----
        if (tid < 256) {
            const int c_i = (0 * 32 + eu) * 9 + er;
            const int c_f = (1 * 32 + eu) * 9 + er;
            const int c_c = (2 * 32 + eu) * 9 + er;
            float gi = pa[c_i] + pa[96 * 9 + c_i] + xi;
            float gf = pa[c_f] + pa[96 * 9 + c_f] + xf;
            float gc = pa[c_c] + pa[96 * 9 + c_c] + xc;
            float iv = sigmoid_f(gi);
            float fv = sigmoid_f(gf);
            float cin = tanh_f(gc);
            cst = fv * cst + iv * cin;
            float hv = tanh_f(cst);
            __stcg(&g_h[((size_t)(nbuf * GROUPS + g) * 8 + er) * U_ + eu + u_base], hv);
            out[((size_t)b * T_ + t) * U_ + ug] = hv;
            __threadfence();
        }
        __syncthreads();

        // ---- group barrier (monotonic counter) ----
        if (tid == 0) {
            atomicAdd(&g_cnt[g * 32], 1);
            const int target = CPG * (t + 1);
            while (*vcnt < target) { }
        }
        __syncthreads();

        // ---- refill hd with h_{t+1} ----
        {
            const float* gh = g_h + (size_t)(nbuf * GROUPS + g) * 8 * U_;
            for (int idx = tid; idx < 8 * U_; idx += RTHREADS) {
                int r = idx >> 9, k = idx & (U_ - 1);
                hd[r * HD_STRIDE + k] = dup2(__ldcg(&gh[idx]));
            }
        }
        __syncthreads();
    }
}

// ============================================================================
extern "C" void kernel_launch(void* const* d_in, const int* in_sizes, int n_in,
                              void* d_out, int out_size) {
    const float* x    = (const float*)d_in[0];
    const float* w_xi = (const float*)d_in[1];
    const float* w_xf = (const float*)d_in[2];
    const float* w_xc = (const float*)d_in[3];
    const float* w_hi = (const float*)d_in[4];
    const float* w_hf = (const float*)d_in[5];
    const float* w_hc = (const float*)d_in[6];
    const float* b_i  = (const float*)d_in[7];
    const float* b_f  = (const float*)d_in[8];
    const float* b_c  = (const float*)d_in[9];
    const float* h0   = (const float*)d_in[10];
    const float* c0   = (const float*)d_in[11];
    float* out = (float*)d_out;

    static bool attr_set = false;
    if (!attr_set) {
        cudaFuncSetAttribute(recur_kernel,
                             cudaFuncAttributeMaxDynamicSharedMemorySize, RSMEM);
        attr_set = true;
    }

    init_kernel<<<32, 256>>>(h0);
    xproj_kernel<<<dim3(U_ / 128, (B_ * T_) / 128, 3), 256>>>(
        x, w_xi, w_xf, w_xc, b_i, b_f, b_c);
    recur_kernel<<<GROUPS * CPG, RTHREADS, RSMEM>>>(w_hi, w_hf, w_hc, c0, out);
}

// round 15
// speedup vs baseline: 1.5567x; 1.5567x over previous
#include <cuda_runtime.h>
#include <cstdint>

// NOGLSTM: B=64, T=512, D=256, U=512
#define B_  64
#define T_  512
#define D_  256
#define U_  512
#define GROUPS 8          // batch groups (8 rows each)
#define CPG    16         // CTAs per group
#define RTHREADS 512      // recurrence kernel threads (16 warps)

typedef unsigned long long ull;

// ----------------------------- device scratch ------------------------------
__device__ float g_xproj[(size_t)T_ * B_ * 3 * U_];   // [t][b][gate][u]
__device__ float g_h[2 * GROUPS * U_ * 8];            // [buf][g][u][r]  (transposed!)
__device__ int   g_cnt[GROUPS * 32];                  // padded counters

// ----------------------------- helpers -------------------------------------
__device__ __forceinline__ void fma2(ull& acc, ull a, ull b) {
    asm("fma.rn.f32x2 %0, %1, %2, %0;" : "+l"(acc) : "l"(a), "l"(b));
}
__device__ __forceinline__ ull dup2(float v) {
    ull r; asm("mov.b64 %0, {%1, %1};" : "=l"(r) : "f"(v)); return r;
}
__device__ __forceinline__ ull pack2(float lo, float hi) {
    ull r; asm("mov.b64 %0, {%1, %2};" : "=l"(r) : "f"(lo), "f"(hi)); return r;
}
__device__ __forceinline__ void unpack2(ull v, float& lo, float& hi) {
    asm("mov.b64 {%0, %1}, %2;" : "=f"(lo), "=f"(hi) : "l"(v));
}
__device__ __forceinline__ ull add2(ull a, ull b) {
    ull r; asm("add.rn.f32x2 %0, %1, %2;" : "=l"(r) : "l"(a), "l"(b)); return r;
}
__device__ __forceinline__ float sigmoid_f(float x) {
    return __fdividef(1.f, 1.f + __expf(-x));
}
__device__ __forceinline__ float tanh_f(float x) {
    float e = __expf(2.f * x);
    return 1.f - __fdividef(2.f, e + 1.f);
}

// ============================================================================
// init: reset counters, load h0 into buffer 0 (transposed: [g][u][r])
// ============================================================================
__global__ void init_kernel(const float* __restrict__ h0) {
    int tid = blockIdx.x * blockDim.x + threadIdx.x;
    if (tid < GROUPS * 32) g_cnt[tid] = 0;
    for (int idx = tid; idx < GROUPS * U_ * 8; idx += gridDim.x * blockDim.x) {
        int r = idx & 7;
        int k = (idx >> 3) & (U_ - 1);
        int g = idx >> 12;
        g_h[idx] = h0[((size_t)(g * 8 + r) << 9) + k];
    }
}

// ============================================================================
// Phase 1: xproj = x @ w_x* + b_*   (f32x2 tiled GEMM)  [unchanged, passing]
// grid = (U/128=4, 32768/128=256, 3), block = 256
// ============================================================================
__global__ __launch_bounds__(256, 2) void xproj_kernel(
    const float* __restrict__ x,
    const float* __restrict__ wi, const float* __restrict__ wf, const float* __restrict__ wc,
    const float* __restrict__ bi, const float* __restrict__ bf, const float* __restrict__ bc)
{
    __shared__ float As[8][128];   // [k][m]
    __shared__ float Bs[8][128];   // [k][n]

    const int gate = blockIdx.z;
    const float* w    = (gate == 0) ? wi : (gate == 1) ? wf : wc;
    const float* bias = (gate == 0) ? bi : (gate == 1) ? bf : bc;

    const int mBase = blockIdx.y * 128;
    const int uBase = blockIdx.x * 128;
    const int tid = threadIdx.x;
    const int tx = tid & 15;
    const int ty = tid >> 4;

    const int aRow = tid >> 1, aK = (tid & 1) * 4;
    const int bK = tid >> 5, bCol = (tid & 31) * 4;

    ull acc[8][4];
    #pragma unroll
    for (int i = 0; i < 8; ++i)
        #pragma unroll
        for (int j = 0; j < 4; ++j) acc[i][j] = 0ull;

    float4 aReg = *(const float4*)&x[(size_t)(mBase + aRow) * D_ + aK];
    float4 bReg = *(const float4*)&w[(size_t)bK * U_ + uBase + bCol];

    for (int kt = 0; kt < D_ / 8; ++kt) {
        __syncthreads();
        As[aK + 0][aRow] = aReg.x;
        As[aK + 1][aRow] = aReg.y;
        As[aK + 2][aRow] = aReg.z;
        As[aK + 3][aRow] = aReg.w;
        *(float4*)&Bs[bK][bCol] = bReg;
        __syncthreads();
        if (kt + 1 < D_ / 8) {
            aReg = *(const float4*)&x[(size_t)(mBase + aRow) * D_ + (kt + 1) * 8 + aK];
            bReg = *(const float4*)&w[(size_t)((kt + 1) * 8 + bK) * U_ + uBase + bCol];
        }
        #pragma unroll
        for (int k = 0; k < 8; ++k) {
            float4 aA = *(const float4*)&As[k][ty * 4];
            float4 aB = *(const float4*)&As[k][64 + ty * 4];
            ulonglong2 b0 = *(const ulonglong2*)&Bs[k][tx * 4];
            ulonglong2 b1 = *(const ulonglong2*)&Bs[k][64 + tx * 4];
            float av[8] = {aA.x, aA.y, aA.z, aA.w, aB.x, aB.y, aB.z, aB.w};
            #pragma unroll
            for (int i = 0; i < 8; ++i) {
                ull ad = dup2(av[i]);
                fma2(acc[i][0], ad, b0.x);
                fma2(acc[i][1], ad, b0.y);
                fma2(acc[i][2], ad, b1.x);
                fma2(acc[i][3], ad, b1.y);
            }
        }
    }

    float4 biasA = *(const float4*)&bias[uBase + tx * 4];
    float4 biasB = *(const float4*)&bias[uBase + 64 + tx * 4];

    #pragma unroll
    for (int i = 0; i < 8; ++i) {
        int m = (i < 4) ? (mBase + ty * 4 + i) : (mBase + 64 + ty * 4 + (i - 4));
        int tt = m & (T_ - 1);
        int bb = m >> 9;
        float l0, h0v, l1, h1v;
        unpack2(acc[i][0], l0, h0v);
        unpack2(acc[i][1], l1, h1v);
        float4 v0 = {l0 + biasA.x, h0v + biasA.y, l1 + biasA.z, h1v + biasA.w};
        unpack2(acc[i][2], l0, h0v);
        unpack2(acc[i][3], l1, h1v);
        float4 v1 = {l0 + biasB.x, h0v + biasB.y, l1 + biasB.z, h1v + biasB.w};
        float* op = g_xproj + ((size_t)(tt * B_ + bb) * 3 + gate) * U_;
        *(float4*)&op[uBase + tx * 4]      = v0;
        *(float4*)&op[uBase + 64 + tx * 4] = v1;
    }
}

// ============================================================================
// Phase 2: persistent recurrence. 128 CTAs = 8 groups x 16. 512 threads.
//
// W layout: Wt[col][k] column-major, col = gate*32 + u_local, stride 516
//   (4*l mod 32 bank pattern -> conflict-free LDS.128 in 8-lane phases).
// h staging: hd[k][rp] ull = (h[2rp][k], h[2rp+1][k])  -- row-pair packed,
//   read warp-uniform (broadcast, N=1) in the GEMM.
// Warp w (0..15) covers k in [32w, 32w+32), all 96 cols (lane l -> unit l,
//   3 gates). acc[3][4] ull = preact row-pairs.
// Partials: warps 0-7 store pa, warps 8-15 RMW-add into pa (24 KB, aliased
//   over hd). Epilogue: 256 threads (r,u) sum 8 partials/gate + gate math.
// ============================================================================
#define WT_STRIDE 516
#define WT_BYTES  (96 * WT_STRIDE * 4)        // 198144
#define PA_ULLS   3072                        // 16? -> 8 warps * 12 ull * 32 lanes
#define RSMEM     (WT_BYTES + PA_ULLS * 8)    // 222720

__global__ __launch_bounds__(RTHREADS, 1) void recur_kernel(
    const float* __restrict__ whi, const float* __restrict__ whf,
    const float* __restrict__ whc, const float* __restrict__ c0,
    float* __restrict__ out)
{
    extern __shared__ char smem_raw[];
    float* Wt = (float*)smem_raw;
    ull*   hd = (ull*)(smem_raw + WT_BYTES);    // 2048 ulls used for h staging
    ull*   pa = hd;                              // 3072 ulls, aliased (phased)
    float2* paf = (float2*)pa;

    const int tid = threadIdx.x;
    const int g   = blockIdx.x >> 4;
    const int cg  = blockIdx.x & 15;
    const int u_base = cg * 32;

    const int w    = tid >> 5;
    const int lane = tid & 31;

    // ---- load W slices column-major: Wt[gate*32+uu][k] ----
    for (int idx = tid; idx < 96 * U_; idx += RTHREADS) {
        int c = idx % 96;          // col
        int k = idx / 96;          // consecutive idx -> consecutive c (coalesced reads)
        int gate = c >> 5;
        int uu = c & 31;
        const float* wsrc = (gate == 0) ? whi : (gate == 1) ? whf : whc;
        Wt[c * WT_STRIDE + k] = wsrc[(size_t)k * U_ + u_base + uu];
    }

    // ---- epilogue thread state: r = tid>>5 (warp id 0..7), u = lane ----
    const int er = w;              // rows 0..7 for first 8 warps
    const int eu = lane;
    const int b  = g * 8 + er;
    const int ug = u_base + eu;
    float cst = 0.f;
    if (tid < 256) cst = c0[(size_t)b * U_ + ug];

    // ---- GEMM pointers ----
    const int kbeg = w * 32;
    const float* pI = Wt + (0 * 32 + lane) * WT_STRIDE + kbeg;
    const float* pF = Wt + (1 * 32 + lane) * WT_STRIDE + kbeg;
    const float* pC = Wt + (2 * 32 + lane) * WT_STRIDE + kbeg;
    const ull*   hp = hd + kbeg * 4;

    // ---- preload hd with h_0 (buf 0) ----
    {
        const float* gh = g_h + (size_t)g * U_ * 8;
        #pragma unroll
        for (int n = 0; n < 4; ++n) {
            int idx = tid + n * RTHREADS;          // 0..2047
            int k = idx >> 2, rp = idx & 3;
            float2 v = __ldcg((const float2*)&gh[(size_t)k * 8 + 2 * rp]);
            hd[idx] = pack2(v.x, v.y);
        }
    }
    __syncthreads();

    volatile int* vcnt = &g_cnt[g * 32];

    for (int t = 0; t < T_; ++t) {
        const int nbuf = (t + 1) & 1;

        // prefetch xproj (latency hidden under GEMM)
        float xi = 0.f, xf = 0.f, xc = 0.f;
        if (tid < 256) {
            const float* xp = g_xproj + ((size_t)(t * B_ + b) * 3) * U_ + ug;
            xi = __ldg(xp);
            xf = __ldg(xp + U_);
            xc = __ldg(xp + 2 * U_);
        }

        // ---- GEMM: all 96 cols, 32 k per warp ----
        ull acc[3][4];
        #pragma unroll
        for (int gg = 0; gg < 3; ++gg)
            #pragma unroll
            for (int rp = 0; rp < 4; ++rp) acc[gg][rp] = 0ull;

        #pragma unroll 4
        for (int kb = 0; kb < 8; ++kb) {
            float4 wi4 = *(const float4*)(pI + kb * 4);
            float4 wf4 = *(const float4*)(pF + kb * 4);
            float4 wc4 = *(const float4*)(pC + kb * 4);
            const float wia[4] = {wi4.x, wi4.y, wi4.z, wi4.w};
            const float wfa[4] = {wf4.x, wf4.y, wf4.z, wf4.w};
            const float wca[4] = {wc4.x, wc4.y, wc4.z, wc4.w};
            #pragma unroll
            for (int j = 0; j < 4; ++j) {
                const ull* hk = hp + (kb * 4 + j) * 4;
                ulonglong2 h01 = *(const ulonglong2*)(hk);
                ulonglong2 h23 = *(const ulonglong2*)(hk + 2);
                ull wi2 = dup2(wia[j]);
                ull wf2 = dup2(wfa[j]);
                ull wc2 = dup2(wca[j]);
                fma2(acc[0][0], h01.x, wi2);
                fma2(acc[0][1], h01.y, wi2);
                fma2(acc[0][2], h23.x, wi2);
                fma2(acc[0][3], h23.y, wi2);
                fma2(acc[1][0], h01.x, wf2);
                fma2(acc[1][1], h01.y, wf2);
                fma2(acc[1][2], h23.x, wf2);
                fma2(acc[1][3], h23.y, wf2);
                fma2(acc[2][0], h01.x, wc2);
                fma2(acc[2][1], h01.y, wc2);
                fma2(acc[2][2], h23.x, wc2);
                fma2(acc[2][3], h23.y, wc2);
            }
        }
        __syncthreads();                       // hd reads done -> pa may be written

        // ---- partials phase 1: warps 0-7 store ----
        if (w < 8) {
            ull* p = pa + (w * 12) * 32 + lane;
            #pragma unroll
            for (int gg = 0; gg < 3; ++gg)
                #pragma unroll
                for (int rp = 0; rp < 4; ++rp)
                    p[(gg * 4 + rp) * 32] = acc[gg][rp];
        }
        __syncthreads();

        // ---- partials phase 2: warps 8-15 read-add-write ----
        if (w >= 8) {
            ull* p = pa + ((w - 8) * 12) * 32 + lane;
            #pragma unroll
            for (int gg = 0; gg < 3; ++gg)
                #pragma unroll
                for (int rp = 0; rp < 4; ++rp)
                    p[(gg * 4 + rp) * 32] = add2(p[(gg * 4 + rp) * 32], acc[gg][rp]);
        }
        __syncthreads();

        // ---- epilogue: sum 8 partials/gate, gate math, h exchange ----
        if (tid < 256) {
            const int rp = er >> 1;
            const int hf = er & 1;
            float si = 0.f, sf = 0.f, sc = 0.f;
            #pragma unroll
            for (int w8 = 0; w8 < 8; ++w8) {
                float2 vi = paf[(w8 * 12 + 0 * 4 + rp) * 32 + eu];
                float2 vf = paf[(w8 * 12 + 1 * 4 + rp) * 32 + eu];
                float2 vc = paf[(w8 * 12 + 2 * 4 + rp) * 32 + eu];
                si += hf ? vi.y : vi.x;
                sf += hf ? vf.y : vf.x;
                sc += hf ? vc.y : vc.x;
            }
            float iv  = sigmoid_f(si + xi);
            float fv  = sigmoid_f(sf + xf);
            float cin = tanh_f(sc + xc);
            cst = fv * cst + iv * cin;
            float hv = tanh_f(cst);
            __stcg(&g_h[((size_t)(nbuf * GROUPS + g) * U_ + ug) * 8 + er], hv);
            out[((size_t)b * T_ + t) * U_ + ug] = hv;
            __threadfence();
        }
        __syncthreads();

        // ---- group barrier (monotonic counter) ----
        if (tid == 0) {
            atomicAdd(&g_cnt[g * 32], 1);
            const int target = CPG * (t + 1);
            while (*vcnt < target) { }
        }
        __syncthreads();

        // ---- refill hd with h_{t+1} (overwrites pa region) ----
        {
            const float* gh = g_h + (size_t)(nbuf * GROUPS + g) * U_ * 8;
            #pragma unroll
            for (int n = 0; n < 4; ++n) {
                int idx = tid + n * RTHREADS;
                int k = idx >> 2, rp = idx & 3;
                float2 v = __ldcg((const float2*)&gh[(size_t)k * 8 + 2 * rp]);
                hd[idx] = pack2(v.x, v.y);
            }
        }
        __syncthreads();
    }
}

// ============================================================================
extern "C" void kernel_launch(void* const* d_in, const int* in_sizes, int n_in,
                              void* d_out, int out_size) {
    const float* x    = (const float*)d_in[0];
    const float* w_xi = (const float*)d_in[1];
    const float* w_xf = (const float*)d_in[2];
    const float* w_xc = (const float*)d_in[3];
    const float* w_hi = (const float*)d_in[4];
    const float* w_hf = (const float*)d_in[5];
    const float* w_hc = (const float*)d_in[6];
    const float* b_i  = (const float*)d_in[7];
    const float* b_f  = (const float*)d_in[8];
    const float* b_c  = (const float*)d_in[9];
    const float* h0   = (const float*)d_in[10];
    const float* c0   = (const float*)d_in[11];
    float* out = (float*)d_out;

    static bool attr_set = false;
    if (!attr_set) {
        cudaFuncSetAttribute(recur_kernel,
                             cudaFuncAttributeMaxDynamicSharedMemorySize, RSMEM);
        attr_set = true;
    }

    init_kernel<<<32, 256>>>(h0);
    xproj_kernel<<<dim3(U_ / 128, (B_ * T_) / 128, 3), 256>>>(
        x, w_xi, w_xf, w_xc, b_i, b_f, b_c);
    recur_kernel<<<GROUPS * CPG, RTHREADS, RSMEM>>>(w_hi, w_hf, w_hc, c0, out);
}